// round 7
// baseline (speedup 1.0000x reference)
#include <cuda_runtime.h>
#include <cstdint>

// SPP: out = concat([x, maxpool5(x), maxpool9(x), maxpool13(x)], axis=1)
// x: (16, 512, 64, 64) fp32 -> out: (16, 2048, 64, 64) fp32
//
// maxpool9 = mp5(mp5(x)); maxpool13 = mp5(mp9)  (exact with -inf pad).
// Each 5x5 pool separable: row-max5 then col-max5. One CTA per (n,c) plane.
//
// R6 = R3 tiling (best occupancy/L1 balance) + occupancy-neutral R4 tricks:
//  - B gets 2 guard rows of -inf above and below -> v-pass is 8 unconditional
//    LDS.128 (no predicate/select chains; R3 ALU was 26%).
//  - last level skips the A writeback (result never re-read).
//  - __launch_bounds__(256, 6): cap regs ~42 so 6 CTAs/SM fit (smem 35.9KB
//    x 6 = 215KB < 228KB) -> 48 warps/SM, up from R3's 40.

#define P 68                       // smem row pitch in floats (16B-aligned rows)
#define A_FLOATS (4 + 64 * P)      // 4-float left guard + 64 rows
#define B_FLOATS (68 * P)          // 2 guard + 64 data + 2 guard rows

__device__ __forceinline__ float fmax5(float a, float b, float c, float d, float e) {
    return fmaxf(fmaxf(fmaxf(a, b), fmaxf(c, d)), e);
}

__device__ __forceinline__ float4 vmax5(float4 a, float4 b, float4 c, float4 d, float4 e) {
    float4 r;
    r.x = fmax5(a.x, b.x, c.x, d.x, e.x);
    r.y = fmax5(a.y, b.y, c.y, d.y, e.y);
    r.z = fmax5(a.z, b.z, c.z, d.z, e.z);
    r.w = fmax5(a.w, b.w, c.w, d.w, e.w);
    return r;
}

__global__ __launch_bounds__(256, 6) void spp_kernel(const float* __restrict__ x,
                                                     float* __restrict__ out) {
    __shared__ __align__(16) float Araw[A_FLOATS];
    __shared__ __align__(16) float B[B_FLOATS];   // rows: 0,1 guard | 2..65 | 66,67 guard
    float* A = Araw + 4;  // A[-4..-1] is the guard read by row 0's left halo load

    const float NI = __int_as_float(0xff800000);
    const float4 NI4 = make_float4(NI, NI, NI, NI);

    const int pidx = blockIdx.x;  // plane index: n*512 + c
    const int tid  = threadIdx.x;
    const int n    = pidx >> 9;
    const int c    = pidx & 511;

    const float* gx   = x + (size_t)pidx * 4096;
    float*       gout = out + ((size_t)n * 2048 + (size_t)c) * 4096;

    // ---- Prologue: load plane into A, copy to out chunk 0, init guards ----
    {
        const float4* gx4 = (const float4*)gx;
        float4*       go4 = (float4*)gout;
#pragma unroll
        for (int i = 0; i < 4; i++) {
            int idx  = tid + i * 256;   // float4 index 0..1023
            float4 v = gx4[idx];
            go4[idx] = v;
            int row = idx >> 4;         // 16 float4 per row
            int c4  = idx & 15;
            *(float4*)&A[row * P + c4 * 4] = v;
        }
        if (tid < 64)  *(float4*)&A[tid * P + 64] = NI4;  // right pads cols 64..67
        if (tid == 64) *(float4*)&Araw[0]         = NI4;  // left guard before row 0
        if (tid < 68) {                                   // B guard rows: 4 rows x 17 f4
            int gr = tid / 17, c4 = tid % 17;
            int lrow = (gr < 2) ? gr : (64 + gr);         // rows 0,1,66,67
            *(float4*)&B[lrow * P + c4 * 4] = NI4;
        }
    }
    __syncthreads();

    // h-pass mapping: one row per thread-pair-group, 16-col segment
    const int hrow = tid & 63;
    const int hcs  = tid >> 6;               // col segment 0..3
    const float* hsrc = &A[hrow * P + hcs * 16 - 4];
    float*       hdst = &B[(2 + hrow) * P + hcs * 16];

    // v-pass mapping: 4 cols x 4 rows per thread
    const int vc4 = tid & 15;                // float4 column 0..15
    const int vr0 = (tid >> 4) << 2;         // row base 0,4,...,60
    const float* vsrc  = &B[vr0 * P + vc4 * 4];   // B row vr0 = data row vr0-2
    float*       vdstA = &A[vr0 * P + vc4 * 4];

#pragma unroll
    for (int level = 0; level < 3; level++) {
        // ---- horizontal max5: A -> B (6 LDS.128, 4 STS.128, unpredicated) ----
        {
            float w[24];
#pragma unroll
            for (int k = 0; k < 6; k++) {
                float4 v = *(const float4*)(hsrc + 4 * k);
                w[4 * k + 0] = v.x; w[4 * k + 1] = v.y;
                w[4 * k + 2] = v.z; w[4 * k + 3] = v.w;
            }
#pragma unroll
            for (int m = 0; m < 4; m++) {
                float4 o;
                o.x = fmax5(w[4 * m + 2], w[4 * m + 3], w[4 * m + 4], w[4 * m + 5], w[4 * m + 6]);
                o.y = fmax5(w[4 * m + 3], w[4 * m + 4], w[4 * m + 5], w[4 * m + 6], w[4 * m + 7]);
                o.z = fmax5(w[4 * m + 4], w[4 * m + 5], w[4 * m + 6], w[4 * m + 7], w[4 * m + 8]);
                o.w = fmax5(w[4 * m + 5], w[4 * m + 6], w[4 * m + 7], w[4 * m + 8], w[4 * m + 9]);
                *(float4*)(hdst + 4 * m) = o;
            }
        }
        __syncthreads();

        // ---- vertical max5: B -> A (+final STG.128), fully unpredicated ----
        {
            float4 v[8];
#pragma unroll
            for (int k = 0; k < 8; k++)
                v[k] = *(const float4*)(vsrc + k * P);

            float4* gl4 = (float4*)(gout + (size_t)(level + 1) * 512 * 4096);
#pragma unroll
            for (int j = 0; j < 4; j++) {
                float4 o = vmax5(v[j], v[j + 1], v[j + 2], v[j + 3], v[j + 4]);
                if (level < 2)
                    *(float4*)(vdstA + j * P) = o;
                gl4[(size_t)(vr0 + j) * 16 + vc4] = o;
            }
        }
        if (level < 2) __syncthreads();
    }
}

extern "C" void kernel_launch(void* const* d_in, const int* in_sizes, int n_in,
                              void* d_out, int out_size) {
    const float* x = (const float*)d_in[0];
    float* out = (float*)d_out;
    spp_kernel<<<8192, 256>>>(x, out);  // 16 * 512 planes
}